// round 10
// baseline (speedup 1.0000x reference)
#include <cuda_runtime.h>

#define BB    8
#define NMAX  128
#define HH    192
#define WW    256
#define INV_DOWN 0.125f
#define NBOX  (BB * NMAX)   // 1024 blocks, one per box

// Antiderivative of the bilinear hat kernel, clipped to [-1, 1] (branchless)
__device__ __forceinline__ float hatP(float u) {
    u = fminf(1.0f, fmaxf(-1.0f, u));
    float neg = 0.5f * (u + 1.0f) * (u + 1.0f);
    float pos = 0.5f + u - 0.5f * u * u;
    return (u <= 0.0f) ? neg : pos;
}

__global__ __launch_bounds__(128)
void count_kernel(const float* __restrict__ den,     // [B, 1, H, W]
                  const float* __restrict__ hboxes,  // [B, NMAX, 5]
                  const float* __restrict__ post,    // [B, NMAX, H, W]
                  float* __restrict__ out)           // zeroed by memset node
{
    const int bn = blockIdx.x;
    const int b  = bn >> 7;            // bn / NMAX
    const int t  = threadIdx.x;
    const int w  = t >> 5;
    const int lane = t & 31;

    // Issue ALL box loads up-front (5 independent LDGs, one L2 round-trip),
    // plus this thread's label for num_b. Branch only after they're in flight.
    const float* box = hboxes + (size_t)bn * 5;
    const float bx1 = __ldg(box + 0);
    const float by1 = __ldg(box + 1);
    const float bx2 = __ldg(box + 2);
    const float by2 = __ldg(box + 3);
    const float lab = __ldg(box + 4);
    const float myLab = __ldg(hboxes + (size_t)b * NMAX * 5 + t * 5 + 4);

    if (lab <= 0.0f) return;           // uniform per block

    __shared__ int   s_cnt[4];
    __shared__ float s_sum[4];

    const unsigned bal = __ballot_sync(0xffffffffu, myLab > 0.0f);
    if (lane == 0) s_cnt[w] = __popc(bal);

    const float x1 = bx1 * INV_DOWN;
    const float y1 = by1 * INV_DOWN;
    const float x2 = bx2 * INV_DOWN;
    const float y2 = by2 * INV_DOWN;

    const int ix0 = max(0, (int)floorf(x1) - 1);
    const int ix1 = min(WW - 1, (int)ceilf(x2) + 1);
    const int iy0 = max(0, (int)floorf(y1) - 1);
    const int iy1 = min(HH - 1, (int)ceilf(y2) + 1);
    const int nx = ix1 - ix0 + 1;      // <= 22
    const int ny = iy1 - iy0 + 1;      // <= 22
    const int total = nx * ny;         // <= 484 < 512 = 4 * 128

    // Magic divide: jy = k / nx via umulhi, exact for k < 2^16.
    const unsigned magic =
        (unsigned)(((1ull << 32) + (unsigned)nx - 1) / (unsigned)nx);

    const float* denB  = den  + (size_t)b  * (HH * WW);
    const float* postN = post + (size_t)bn * (HH * WW);

    // Loop-free: each thread owns exactly 4 predicated cells -> 8 loads in flight.
    int   xi[4], yi[4];
    float dv[4], pv[4];
    #pragma unroll
    for (int i = 0; i < 4; i++) {
        const int k  = t + i * 128;
        const int jy = (int)__umulhi((unsigned)k, magic);
        const int jx = k - jy * nx;
        xi[i] = ix0 + jx;
        yi[i] = iy0 + jy;
        const bool m = (k < total);
        const int idx = yi[i] * WW + xi[i];
        dv[i] = m ? __ldg(denB  + idx) : 0.0f;
        pv[i] = m ? __ldg(postN + idx) : 0.0f;
    }

    float acc = 0.0f;
    #pragma unroll
    for (int i = 0; i < 4; i++) {
        const float wxv = hatP(x2 - (float)xi[i]) - hatP(x1 - (float)xi[i]);
        const float wyv = hatP(y2 - (float)yi[i]) - hatP(y1 - (float)yi[i]);
        acc += (wxv * wyv) * (dv[i] * pv[i]);
    }

    // Warp reduce -> smem -> one sync -> leader RED to out.
    #pragma unroll
    for (int o = 16; o > 0; o >>= 1)
        acc += __shfl_down_sync(0xffffffffu, acc, o);
    if (lane == 0) s_sum[w] = acc;
    __syncthreads();

    if (t == 0) {
        const float count = s_sum[0] + s_sum[1] + s_sum[2] + s_sum[3];
        const int   num   = s_cnt[0] + s_cnt[1] + s_cnt[2] + s_cnt[3]; // >= 1
        // per_img = sum_i |c_i - 1| / num_b, division distributed per box.
        atomicAdd(out, fabsf(count - 1.0f) * (1.0f / (float)num));
    }
}

extern "C" void kernel_launch(void* const* d_in, const int* in_sizes, int n_in,
                              void* d_out, int out_size)
{
    // metadata order: cls(0), reg(1), off(2), den(3), fboxes(4), hboxes(5),
    //                 ctr_masks(6), post_probs(7)
    const float* den    = (const float*)d_in[3];
    const float* hboxes = (const float*)d_in[5];
    const float* post   = (const float*)d_in[7];
    float* out = (float*)d_out;

    cudaMemsetAsync(out, 0, sizeof(float));          // graph memset node
    count_kernel<<<NBOX, 128>>>(den, hboxes, post, out);
}

// round 11
// speedup vs baseline: 1.2016x; 1.2016x over previous
#include <cuda_runtime.h>

#define BB    8
#define NMAX  128
#define HH    192
#define WW    256
#define INV_DOWN 0.125f
#define NBOX   (BB * NMAX)     // 1024 boxes
#define WPB    4               // warps (=boxes) per CTA
#define GRIDB  (NBOX / WPB)    // 256 CTAs
#define CELLS  16              // cells per lane: 16*32 = 512 >= max support 484

// Antiderivative of the bilinear hat kernel, clipped to [-1, 1] (branchless)
__device__ __forceinline__ float hatP(float u) {
    u = fminf(1.0f, fmaxf(-1.0f, u));
    float neg = 0.5f * (u + 1.0f) * (u + 1.0f);
    float pos = 0.5f + u - 0.5f * u * u;
    return (u <= 0.0f) ? neg : pos;
}

__global__ __launch_bounds__(WPB * 32)
void count_kernel(const float* __restrict__ den,     // [B, 1, H, W]
                  const float* __restrict__ hboxes,  // [B, NMAX, 5]
                  const float* __restrict__ post,    // [B, NMAX, H, W]
                  float* __restrict__ out)           // zeroed by memset node
{
    const int w    = threadIdx.x >> 5;          // warp in CTA
    const int lane = threadIdx.x & 31;
    const int bn   = blockIdx.x * WPB + w;      // this warp's box
    const int b    = bn >> 7;                   // image index

    // Issue all scalar loads up-front: 5 box fields + 4 labels for num_b
    // (one L2 round-trip total, all independent).
    const float* box = hboxes + (size_t)bn * 5;
    const float bx1 = __ldg(box + 0);
    const float by1 = __ldg(box + 1);
    const float bx2 = __ldg(box + 2);
    const float by2 = __ldg(box + 3);
    const float lab = __ldg(box + 4);

    const float* labB = hboxes + (size_t)b * NMAX * 5 + 4;   // label stride 5
    const float l0 = __ldg(labB + (lane      ) * 5);
    const float l1 = __ldg(labB + (lane + 32 ) * 5);
    const float l2 = __ldg(labB + (lane + 64 ) * 5);
    const float l3 = __ldg(labB + (lane + 96 ) * 5);

    if (lab <= 0.0f) return;        // uniform per warp; no barriers anywhere

    // num_b via 4 ballots (covers all 128 labels of this image)
    const int num = __popc(__ballot_sync(0xffffffffu, l0 > 0.0f))
                  + __popc(__ballot_sync(0xffffffffu, l1 > 0.0f))
                  + __popc(__ballot_sync(0xffffffffu, l2 > 0.0f))
                  + __popc(__ballot_sync(0xffffffffu, l3 > 0.0f));   // >= 1

    const float x1 = bx1 * INV_DOWN;
    const float y1 = by1 * INV_DOWN;
    const float x2 = bx2 * INV_DOWN;
    const float y2 = by2 * INV_DOWN;

    const int ix0 = max(0, (int)floorf(x1) - 1);
    const int ix1 = min(WW - 1, (int)ceilf(x2) + 1);
    const int iy0 = max(0, (int)floorf(y1) - 1);
    const int iy1 = min(HH - 1, (int)ceilf(y2) + 1);
    const int nx = ix1 - ix0 + 1;   // <= 22
    const int ny = iy1 - iy0 + 1;   // <= 22
    const int total = nx * ny;      // <= 484 <= 512 = CELLS * 32

    // Magic divide: jy = k / nx via umulhi, exact for k < 2^16.
    const unsigned magic =
        (unsigned)(((1ull << 32) + (unsigned)nx - 1) / (unsigned)nx);

    const float* denB  = den  + (size_t)b  * (HH * WW);
    const float* postN = post + (size_t)bn * (HH * WW);

    // Loop-free: 16 predicated cells per lane -> 32 loads in flight.
    float dv[CELLS], pv[CELLS];
    #pragma unroll
    for (int i = 0; i < CELLS; i++) {
        const int k  = lane + i * 32;
        const int jy = (int)__umulhi((unsigned)k, magic);
        const int jx = k - jy * nx;
        const int idx = (iy0 + jy) * WW + (ix0 + jx);
        const bool m = (k < total);
        dv[i] = m ? __ldg(denB  + idx) : 0.0f;
        pv[i] = m ? __ldg(postN + idx) : 0.0f;
    }

    // Accumulate with 4 independent chains (recompute cell coords; ALU is idle).
    float a0 = 0.0f, a1 = 0.0f, a2 = 0.0f, a3 = 0.0f;
    #pragma unroll
    for (int i = 0; i < CELLS; i += 4) {
        #pragma unroll
        for (int j = 0; j < 4; j++) {
            const int k  = lane + (i + j) * 32;
            const int jy = (int)__umulhi((unsigned)k, magic);
            const int jx = k - jy * nx;
            const float fx = (float)(ix0 + jx);
            const float fy = (float)(iy0 + jy);
            const float wxv = hatP(x2 - fx) - hatP(x1 - fx);
            const float wyv = hatP(y2 - fy) - hatP(y1 - fy);
            const float v = (wxv * wyv) * (dv[i + j] * pv[i + j]);
            if (j == 0) a0 += v; else if (j == 1) a1 += v;
            else if (j == 2) a2 += v; else a3 += v;
        }
    }
    float acc = (a0 + a1) + (a2 + a3);

    // Warp reduce, then one RED per box. No smem, no bar.sync.
    #pragma unroll
    for (int o = 16; o > 0; o >>= 1)
        acc += __shfl_down_sync(0xffffffffu, acc, o);

    if (lane == 0)
        atomicAdd(out, fabsf(acc - 1.0f) * (1.0f / (float)num));
}

extern "C" void kernel_launch(void* const* d_in, const int* in_sizes, int n_in,
                              void* d_out, int out_size)
{
    // metadata order: cls(0), reg(1), off(2), den(3), fboxes(4), hboxes(5),
    //                 ctr_masks(6), post_probs(7)
    const float* den    = (const float*)d_in[3];
    const float* hboxes = (const float*)d_in[5];
    const float* post   = (const float*)d_in[7];
    float* out = (float*)d_out;

    cudaMemsetAsync(out, 0, sizeof(float));          // graph memset node
    count_kernel<<<GRIDB, WPB * 32>>>(den, hboxes, post, out);
}